// round 2
// baseline (speedup 1.0000x reference)
#include <cuda_runtime.h>
#include <math.h>

#define NNODES 100000
#define NEDGES 3200000
#define F 256

// Scratch (allocation-free contract: __device__ globals)
__device__ float g_h[(size_t)NNODES * F];   // 102.4 MB
__device__ float g_q[NNODES];
__device__ float g_k[NNODES];
__device__ float g_m[NNODES];
__device__ float g_s[NNODES];
__device__ float g_c[NEDGES];               // 12.8 MB

// ---------------------------------------------------------------------------
// K0: init m = -inf, s = 0
// ---------------------------------------------------------------------------
__global__ void init_ms_kernel(int n) {
    int i = blockIdx.x * blockDim.x + threadIdx.x;
    if (i < n) { g_m[i] = -INFINITY; g_s[i] = 0.0f; }
}

// ---------------------------------------------------------------------------
// K1: h = x @ Wv + bv   (M x 256) = (M x 256)(256 x 256)
// Classic 128x128 tile, BK=8, 256 threads, 8x8 per thread, float4 I/O.
// ---------------------------------------------------------------------------
__global__ __launch_bounds__(256) void gemm_kernel(
    const float* __restrict__ A,   // x  [M,256]
    const float* __restrict__ B,   // Wv [256,256]
    const float* __restrict__ bias,
    int M)
{
    __shared__ float As[8][128];
    __shared__ float Bs[8][128];

    const int t    = threadIdx.x;
    const int brow = blockIdx.y;
    const int bcol = blockIdx.x;
    const int tr   = t >> 4;       // 0..15
    const int tc   = t & 15;       // 0..15

    // A-tile loader: 128 rows x 8 cols; thread loads one float4
    const int irA = t >> 1;
    const int icA = (t & 1) * 4;
    // B-tile loader: 8 rows x 128 cols; thread loads one float4
    const int irB = t >> 5;
    const int icB = (t & 31) * 4;

    int arow = brow * 128 + irA;
    if (arow >= M) arow = M - 1;            // clamp reads; stores guarded
    const float* aptr = A + (size_t)arow * 256 + icA;
    const float* bptr = B + (size_t)irB * 256 + bcol * 128 + icB;

    float acc[8][8];
    #pragma unroll
    for (int i = 0; i < 8; i++)
        #pragma unroll
        for (int j = 0; j < 8; j++) acc[i][j] = 0.0f;

    for (int k0 = 0; k0 < 256; k0 += 8) {
        float4 a4 = *(const float4*)(aptr + k0);
        float4 b4 = *(const float4*)(bptr + (size_t)k0 * 256);
        As[icA + 0][irA] = a4.x;
        As[icA + 1][irA] = a4.y;
        As[icA + 2][irA] = a4.z;
        As[icA + 3][irA] = a4.w;
        *(float4*)&Bs[irB][icB] = b4;
        __syncthreads();

        #pragma unroll
        for (int kk = 0; kk < 8; kk++) {
            float ra[8], rb[8];
            #pragma unroll
            for (int i = 0; i < 8; i++) ra[i] = As[kk][tr * 8 + i];
            #pragma unroll
            for (int j = 0; j < 8; j++) rb[j] = Bs[kk][tc * 8 + j];
            #pragma unroll
            for (int i = 0; i < 8; i++)
                #pragma unroll
                for (int j = 0; j < 8; j++) acc[i][j] += ra[i] * rb[j];
        }
        __syncthreads();
    }

    const int colBase = bcol * 128 + tc * 8;
    float bv0[8];
    #pragma unroll
    for (int j = 0; j < 8; j++) bv0[j] = bias[colBase + j];

    #pragma unroll
    for (int i = 0; i < 8; i++) {
        int row = brow * 128 + tr * 8 + i;
        if (row < M) {
            float* orow = g_h + (size_t)row * 256 + colBase;
            float4 o0 = make_float4(acc[i][0] + bv0[0], acc[i][1] + bv0[1],
                                    acc[i][2] + bv0[2], acc[i][3] + bv0[3]);
            float4 o1 = make_float4(acc[i][4] + bv0[4], acc[i][5] + bv0[5],
                                    acc[i][6] + bv0[6], acc[i][7] + bv0[7]);
            *(float4*)(orow + 0) = o0;
            *(float4*)(orow + 4) = o1;
        }
    }
}

// ---------------------------------------------------------------------------
// K2: q = h@wq + bq, k = h@wk + bk  — one warp per node
// ---------------------------------------------------------------------------
__global__ __launch_bounds__(256) void qk_kernel(
    const float* __restrict__ wq, const float* __restrict__ bq,
    const float* __restrict__ wk, const float* __restrict__ bk, int n)
{
    int warp = (blockIdx.x * blockDim.x + threadIdx.x) >> 5;
    int lane = threadIdx.x & 31;
    if (warp >= n) return;

    const float4* hrow = (const float4*)(g_h + (size_t)warp * F);
    const float4* q4 = (const float4*)wq;
    const float4* k4 = (const float4*)wk;

    float sq = 0.f, sk = 0.f;
    #pragma unroll
    for (int it = 0; it < 2; it++) {
        int idx = lane + it * 32;
        float4 hv = hrow[idx];
        float4 qv = q4[idx];
        float4 kv = k4[idx];
        sq += hv.x * qv.x + hv.y * qv.y + hv.z * qv.z + hv.w * qv.w;
        sk += hv.x * kv.x + hv.y * kv.y + hv.z * kv.z + hv.w * kv.w;
    }
    #pragma unroll
    for (int o = 16; o; o >>= 1) {
        sq += __shfl_xor_sync(0xFFFFFFFFu, sq, o);
        sk += __shfl_xor_sync(0xFFFFFFFFu, sk, o);
    }
    if (lane == 0) {
        g_q[warp] = sq + bq[0];
        g_k[warp] = sk + bk[0];
    }
}

// ---------------------------------------------------------------------------
// K3: c = leakyrelu(q[src]+k[dst]); segment max into m[dst]
// float atomic max via sign trick (m initialized to -inf)
// ---------------------------------------------------------------------------
__global__ __launch_bounds__(256) void edge_logits_kernel(
    const int* __restrict__ src, const int* __restrict__ dst, int E)
{
    int e = blockIdx.x * blockDim.x + threadIdx.x;
    if (e >= E) return;
    int s_ = src[e], d_ = dst[e];
    float v = g_q[s_] + g_k[d_];
    float c = v > 0.f ? v : 0.2f * v;
    g_c[e] = c;
    if (c >= 0.f)
        atomicMax((int*)&g_m[d_], __float_as_int(c));
    else
        atomicMin((unsigned int*)&g_m[d_], (unsigned int)__float_as_int(c));
}

// ---------------------------------------------------------------------------
// K4: s[dst] += exp(c - m[dst])
// ---------------------------------------------------------------------------
__global__ __launch_bounds__(256) void edge_expsum_kernel(
    const int* __restrict__ dst, int E)
{
    int e = blockIdx.x * blockDim.x + threadIdx.x;
    if (e >= E) return;
    int d_ = dst[e];
    atomicAdd(&g_s[d_], __expf(g_c[e] - g_m[d_]));
}

// ---------------------------------------------------------------------------
// K5: out[dst] += attn * h[src]   — one warp per edge, red.add.v4.f32
// ---------------------------------------------------------------------------
__device__ __forceinline__ void red_add_v4(float* addr, float4 v) {
    asm volatile("red.global.add.v4.f32 [%0], {%1,%2,%3,%4};"
                 :: "l"(addr), "f"(v.x), "f"(v.y), "f"(v.z), "f"(v.w)
                 : "memory");
}

__global__ __launch_bounds__(256) void scatter_kernel(
    const int* __restrict__ src, const int* __restrict__ dst,
    float* __restrict__ out, int E)
{
    int e = blockIdx.x * 8 + (threadIdx.x >> 5);
    int lane = threadIdx.x & 31;
    if (e >= E) return;
    int s_ = src[e], d_ = dst[e];
    float attn = __expf(g_c[e] - g_m[d_]) / g_s[d_];

    const float4* hrow = (const float4*)(g_h + (size_t)s_ * F);
    float* orow = out + (size_t)d_ * F;

    float4 h0 = hrow[lane];
    float4 h1 = hrow[lane + 32];
    red_add_v4(orow + lane * 4,
               make_float4(h0.x * attn, h0.y * attn, h0.z * attn, h0.w * attn));
    red_add_v4(orow + 128 + lane * 4,
               make_float4(h1.x * attn, h1.y * attn, h1.z * attn, h1.w * attn));
}

// ---------------------------------------------------------------------------
extern "C" void kernel_launch(void* const* d_in, const int* in_sizes, int n_in,
                              void* d_out, int out_size)
{
    const float* x  = (const float*)d_in[0];
    const float* Wv = (const float*)d_in[1];
    const float* bv = (const float*)d_in[2];
    const float* wq = (const float*)d_in[3];
    const float* bq = (const float*)d_in[4];
    const float* wk = (const float*)d_in[5];
    const float* bk = (const float*)d_in[6];
    const int*   src = (const int*)d_in[7];
    const int*   dst = (const int*)d_in[8];

    const int M = in_sizes[0] / F;      // 100000
    const int E = in_sizes[7];          // 3200000

    cudaMemsetAsync(d_out, 0, (size_t)out_size * sizeof(float));
    init_ms_kernel<<<(M + 255) / 256, 256>>>(M);

    dim3 ggrid(2, (M + 127) / 128);
    gemm_kernel<<<ggrid, 256>>>(x, Wv, bv, M);

    qk_kernel<<<(M + 7) / 8, 256>>>(wq, bq, wk, bk, M);
    edge_logits_kernel<<<(E + 255) / 256, 256>>>(src, dst, E);
    edge_expsum_kernel<<<(E + 255) / 256, 256>>>(dst, E);
    scatter_kernel<<<(E + 7) / 8, 256>>>(src, dst, (float*)d_out, E);
}

// round 3
// speedup vs baseline: 1.0101x; 1.0101x over previous
#include <cuda_runtime.h>
#include <math.h>

#define NNODES 100000
#define NEDGES 3200000
#define F 256

// Scratch (allocation-free contract: __device__ globals)
__device__ float g_h[(size_t)NNODES * F];   // 102.4 MB
__device__ float g_q[NNODES];
__device__ float g_k[NNODES];
__device__ float g_m[NNODES];
__device__ float g_s[NNODES];
__device__ float g_c[NEDGES];               // 12.8 MB

// ---------------------------------------------------------------------------
// K0: init m = -inf, s = 0
// ---------------------------------------------------------------------------
__global__ void init_ms_kernel(int n) {
    int i = blockIdx.x * blockDim.x + threadIdx.x;
    if (i < n) { g_m[i] = -INFINITY; g_s[i] = 0.0f; }
}

// ---------------------------------------------------------------------------
// K1: h = x @ Wv + bv   (M x 256) = (M x 256)(256 x 256)
// Classic 128x128 tile, BK=8, 256 threads, 8x8 per thread, float4 I/O.
// ---------------------------------------------------------------------------
__global__ __launch_bounds__(256) void gemm_kernel(
    const float* __restrict__ A,   // x  [M,256]
    const float* __restrict__ B,   // Wv [256,256]
    const float* __restrict__ bias,
    int M)
{
    __shared__ float As[8][128];
    __shared__ float Bs[8][128];

    const int t    = threadIdx.x;
    const int brow = blockIdx.y;
    const int bcol = blockIdx.x;
    const int tr   = t >> 4;       // 0..15
    const int tc   = t & 15;       // 0..15

    // A-tile loader: 128 rows x 8 cols; thread loads one float4
    const int irA = t >> 1;
    const int icA = (t & 1) * 4;
    // B-tile loader: 8 rows x 128 cols; thread loads one float4
    const int irB = t >> 5;
    const int icB = (t & 31) * 4;

    int arow = brow * 128 + irA;
    if (arow >= M) arow = M - 1;            // clamp reads; stores guarded
    const float* aptr = A + (size_t)arow * 256 + icA;
    const float* bptr = B + (size_t)irB * 256 + bcol * 128 + icB;

    float acc[8][8];
    #pragma unroll
    for (int i = 0; i < 8; i++)
        #pragma unroll
        for (int j = 0; j < 8; j++) acc[i][j] = 0.0f;

    for (int k0 = 0; k0 < 256; k0 += 8) {
        float4 a4 = *(const float4*)(aptr + k0);
        float4 b4 = *(const float4*)(bptr + (size_t)k0 * 256);
        As[icA + 0][irA] = a4.x;
        As[icA + 1][irA] = a4.y;
        As[icA + 2][irA] = a4.z;
        As[icA + 3][irA] = a4.w;
        *(float4*)&Bs[irB][icB] = b4;
        __syncthreads();

        #pragma unroll
        for (int kk = 0; kk < 8; kk++) {
            float ra[8], rb[8];
            #pragma unroll
            for (int i = 0; i < 8; i++) ra[i] = As[kk][tr * 8 + i];
            #pragma unroll
            for (int j = 0; j < 8; j++) rb[j] = Bs[kk][tc * 8 + j];
            #pragma unroll
            for (int i = 0; i < 8; i++)
                #pragma unroll
                for (int j = 0; j < 8; j++) acc[i][j] += ra[i] * rb[j];
        }
        __syncthreads();
    }

    const int colBase = bcol * 128 + tc * 8;
    float bv0[8];
    #pragma unroll
    for (int j = 0; j < 8; j++) bv0[j] = bias[colBase + j];

    #pragma unroll
    for (int i = 0; i < 8; i++) {
        int row = brow * 128 + tr * 8 + i;
        if (row < M) {
            float* orow = g_h + (size_t)row * 256 + colBase;
            float4 o0 = make_float4(acc[i][0] + bv0[0], acc[i][1] + bv0[1],
                                    acc[i][2] + bv0[2], acc[i][3] + bv0[3]);
            float4 o1 = make_float4(acc[i][4] + bv0[4], acc[i][5] + bv0[5],
                                    acc[i][6] + bv0[6], acc[i][7] + bv0[7]);
            *(float4*)(orow + 0) = o0;
            *(float4*)(orow + 4) = o1;
        }
    }
}

// ---------------------------------------------------------------------------
// K2: q = h@wq + bq, k = h@wk + bk  — one warp per node
// ---------------------------------------------------------------------------
__global__ __launch_bounds__(256) void qk_kernel(
    const float* __restrict__ wq, const float* __restrict__ bq,
    const float* __restrict__ wk, const float* __restrict__ bk, int n)
{
    int warp = (blockIdx.x * blockDim.x + threadIdx.x) >> 5;
    int lane = threadIdx.x & 31;
    if (warp >= n) return;

    const float4* hrow = (const float4*)(g_h + (size_t)warp * F);
    const float4* q4 = (const float4*)wq;
    const float4* k4 = (const float4*)wk;

    float sq = 0.f, sk = 0.f;
    #pragma unroll
    for (int it = 0; it < 2; it++) {
        int idx = lane + it * 32;
        float4 hv = hrow[idx];
        float4 qv = q4[idx];
        float4 kv = k4[idx];
        sq += hv.x * qv.x + hv.y * qv.y + hv.z * qv.z + hv.w * qv.w;
        sk += hv.x * kv.x + hv.y * kv.y + hv.z * kv.z + hv.w * kv.w;
    }
    #pragma unroll
    for (int o = 16; o; o >>= 1) {
        sq += __shfl_xor_sync(0xFFFFFFFFu, sq, o);
        sk += __shfl_xor_sync(0xFFFFFFFFu, sk, o);
    }
    if (lane == 0) {
        g_q[warp] = sq + bq[0];
        g_k[warp] = sk + bk[0];
    }
}

// ---------------------------------------------------------------------------
// K3: c = leakyrelu(q[src]+k[dst]); segment max into m[dst]
// float atomic max via sign trick (m initialized to -inf)
// ---------------------------------------------------------------------------
__global__ __launch_bounds__(256) void edge_logits_kernel(
    const int* __restrict__ src, const int* __restrict__ dst, int E)
{
    int e = blockIdx.x * blockDim.x + threadIdx.x;
    if (e >= E) return;
    int s_ = src[e], d_ = dst[e];
    float v = g_q[s_] + g_k[d_];
    float c = v > 0.f ? v : 0.2f * v;
    g_c[e] = c;
    if (c >= 0.f)
        atomicMax((int*)&g_m[d_], __float_as_int(c));
    else
        atomicMin((unsigned int*)&g_m[d_], (unsigned int)__float_as_int(c));
}

// ---------------------------------------------------------------------------
// K4: s[dst] += exp(c - m[dst])
// ---------------------------------------------------------------------------
__global__ __launch_bounds__(256) void edge_expsum_kernel(
    const int* __restrict__ dst, int E)
{
    int e = blockIdx.x * blockDim.x + threadIdx.x;
    if (e >= E) return;
    int d_ = dst[e];
    atomicAdd(&g_s[d_], __expf(g_c[e] - g_m[d_]));
}

// ---------------------------------------------------------------------------
// K5: out[dst] += attn * h[src]   — one warp per edge, red.add.v4.f32
// ---------------------------------------------------------------------------
__device__ __forceinline__ void red_add_v4(float* addr, float4 v) {
    asm volatile("red.global.add.v4.f32 [%0], {%1,%2,%3,%4};"
                 :: "l"(addr), "f"(v.x), "f"(v.y), "f"(v.z), "f"(v.w)
                 : "memory");
}

__global__ __launch_bounds__(256) void scatter_kernel(
    const int* __restrict__ src, const int* __restrict__ dst,
    float* __restrict__ out, int E)
{
    int e = blockIdx.x * 8 + (threadIdx.x >> 5);
    int lane = threadIdx.x & 31;
    if (e >= E) return;
    int s_ = src[e], d_ = dst[e];
    float attn = __expf(g_c[e] - g_m[d_]) / g_s[d_];

    const float4* hrow = (const float4*)(g_h + (size_t)s_ * F);
    float* orow = out + (size_t)d_ * F;

    float4 h0 = hrow[lane];
    float4 h1 = hrow[lane + 32];
    red_add_v4(orow + lane * 4,
               make_float4(h0.x * attn, h0.y * attn, h0.z * attn, h0.w * attn));
    red_add_v4(orow + 128 + lane * 4,
               make_float4(h1.x * attn, h1.y * attn, h1.z * attn, h1.w * attn));
}

// ---------------------------------------------------------------------------
extern "C" void kernel_launch(void* const* d_in, const int* in_sizes, int n_in,
                              void* d_out, int out_size)
{
    const float* x  = (const float*)d_in[0];
    const float* Wv = (const float*)d_in[1];
    const float* bv = (const float*)d_in[2];
    const float* wq = (const float*)d_in[3];
    const float* bq = (const float*)d_in[4];
    const float* wk = (const float*)d_in[5];
    const float* bk = (const float*)d_in[6];
    const int*   src = (const int*)d_in[7];
    const int*   dst = (const int*)d_in[8];

    const int M = in_sizes[0] / F;      // 100000
    const int E = in_sizes[7];          // 3200000

    cudaMemsetAsync(d_out, 0, (size_t)out_size * sizeof(float));
    init_ms_kernel<<<(M + 255) / 256, 256>>>(M);

    dim3 ggrid(2, (M + 127) / 128);
    gemm_kernel<<<ggrid, 256>>>(x, Wv, bv, M);

    qk_kernel<<<(M + 7) / 8, 256>>>(wq, bq, wk, bk, M);
    edge_logits_kernel<<<(E + 255) / 256, 256>>>(src, dst, E);
    edge_expsum_kernel<<<(E + 255) / 256, 256>>>(dst, E);
    scatter_kernel<<<(E + 7) / 8, 256>>>(src, dst, (float*)d_out, E);
}